// round 8
// baseline (speedup 1.0000x reference)
#include <cuda_runtime.h>
#include <cuda_bf16.h>
#include <cstdint>
#include <math.h>

#define DM 2048
#define HID 8192
#define NE 8
#define STOK 8192
#define CAPE 2048

// ---------------- scratch (device globals, zero-init) --------------------------
__device__ unsigned g_disp_hi[(size_t)NE * CAPE * DM / 2];   // [e][m][k2]
__device__ unsigned g_disp_lo[(size_t)NE * CAPE * DM / 2];
__device__ unsigned g_h_hi[(size_t)NE * CAPE * HID / 2];     // [e][m][k2]
__device__ unsigned g_h_lo[(size_t)NE * CAPE * HID / 2];
__device__ unsigned g_w1hi[(size_t)NE * HID * (DM / 2)];     // [e][n][k2]  (transposed pack)
__device__ unsigned g_w1lo[(size_t)NE * HID * (DM / 2)];
__device__ unsigned g_w2hi[(size_t)NE * DM * (HID / 2)];     // [e][n][k2]
__device__ unsigned g_w2lo[(size_t)NE * DM * (HID / 2)];
__device__ float    g_eo[(size_t)NE * CAPE * DM];
__device__ int      g_idx[STOK * 2];
__device__ float    g_gate[STOK * 2];
__device__ int      g_pos[STOK * 2];
__device__ float    g_gv[STOK * 2];

// ---------------- helpers -------------------------------------------------------
__device__ __forceinline__ uint32_t smem_u32(const void* p) {
    uint32_t a;
    asm("{ .reg .u64 t; cvta.to.shared.u64 t, %1; cvt.u32.u64 %0, t; }" : "=r"(a) : "l"(p));
    return a;
}
__device__ __forceinline__ void cp16(uint32_t dst, const void* src) {
    asm volatile("cp.async.cg.shared.global [%0], [%1], 16;" :: "r"(dst), "l"(src) : "memory");
}
// pack k-pair (even e, odd o) into bf16x2 hi word + residual lo word; low16 = even
__device__ __forceinline__ void packsplit2(float e, float o, unsigned& hi, unsigned& lo) {
    __nv_bfloat162 h2, l2;
    h2.x = __float2bfloat16_rn(e);
    h2.y = __float2bfloat16_rn(o);
    l2.x = __float2bfloat16_rn(e - __bfloat162float(h2.x));
    l2.y = __float2bfloat16_rn(o - __bfloat162float(h2.y));
    hi = *reinterpret_cast<unsigned*>(&h2);
    lo = *reinterpret_cast<unsigned*>(&l2);
}
__device__ __forceinline__ void mma16(float4& d, const unsigned* a, unsigned b0, unsigned b1) {
    asm volatile(
        "mma.sync.aligned.m16n8k16.row.col.f32.bf16.bf16.f32 "
        "{%0,%1,%2,%3}, {%4,%5,%6,%7}, {%8,%9}, {%0,%1,%2,%3};"
        : "+f"(d.x), "+f"(d.y), "+f"(d.z), "+f"(d.w)
        : "r"(a[0]), "r"(a[1]), "r"(a[2]), "r"(a[3]), "r"(b0), "r"(b1));
}
__device__ __forceinline__ void ldsm4(unsigned* r, uint32_t a) {
    asm volatile("ldmatrix.sync.aligned.m8n8.x4.shared.b16 {%0,%1,%2,%3}, [%4];"
                 : "=r"(r[0]), "=r"(r[1]), "=r"(r[2]), "=r"(r[3]) : "r"(a));
}

// ---------------- gate ----------------------------------------------------------
__global__ void gate_kernel(const float* __restrict__ x, const float* __restrict__ wg)
{
    int gw = (blockIdx.x * blockDim.x + threadIdx.x) >> 5;
    int lane = threadIdx.x & 31;
    if (gw >= STOK) return;
    const float* xr = x + (size_t)gw * DM;
    float acc[NE];
#pragma unroll
    for (int e = 0; e < NE; e++) acc[e] = 0.f;
    for (int d = lane; d < DM; d += 32) {
        float xv = __ldg(xr + d);
        const float4* w = reinterpret_cast<const float4*>(wg + (size_t)d * NE);
        float4 w0 = __ldg(w), w1 = __ldg(w + 1);
        acc[0] = fmaf(xv, w0.x, acc[0]); acc[1] = fmaf(xv, w0.y, acc[1]);
        acc[2] = fmaf(xv, w0.z, acc[2]); acc[3] = fmaf(xv, w0.w, acc[3]);
        acc[4] = fmaf(xv, w1.x, acc[4]); acc[5] = fmaf(xv, w1.y, acc[5]);
        acc[6] = fmaf(xv, w1.z, acc[6]); acc[7] = fmaf(xv, w1.w, acc[7]);
    }
#pragma unroll
    for (int off = 16; off > 0; off >>= 1)
#pragma unroll
        for (int e = 0; e < NE; e++) acc[e] += __shfl_down_sync(0xffffffffu, acc[e], off);
    if (lane == 0) {
        float mx = acc[0];
#pragma unroll
        for (int e = 1; e < NE; e++) mx = fmaxf(mx, acc[e]);
        float p[NE]; float sum = 0.f;
#pragma unroll
        for (int e = 0; e < NE; e++) { p[e] = expf(acc[e] - mx); sum += p[e]; }
        float inv = 1.f / sum;
#pragma unroll
        for (int e = 0; e < NE; e++) p[e] *= inv;
        int i1 = 0;
#pragma unroll
        for (int e = 1; e < NE; e++) if (p[e] > p[i1]) i1 = e;
        int i2 = (i1 == 0) ? 1 : 0;
#pragma unroll
        for (int e = 0; e < NE; e++) if (e != i1 && p[e] > p[i2]) i2 = e;
        float denom = fmaxf(p[i1] + p[i2], 1e-9f);
        g_idx[gw * 2 + 0] = i1;             g_idx[gw * 2 + 1] = i2;
        g_gate[gw * 2 + 0] = p[i1] / denom; g_gate[gw * 2 + 1] = p[i2] / denom;
    }
}

// ---------------- positions -----------------------------------------------------
__global__ void pos_kernel()
{
    int e = blockIdx.x;
    __shared__ int sc[1024];
    int base = 0;
    for (int s = 0; s < 2; ++s) {
        for (int chunk = 0; chunk < STOK; chunk += 1024) {
            int t = chunk + threadIdx.x;
            int m = (g_idx[t * 2 + s] == e) ? 1 : 0;
            sc[threadIdx.x] = m;
            __syncthreads();
            for (int off = 1; off < 1024; off <<= 1) {
                int v = (threadIdx.x >= off) ? sc[threadIdx.x - off] : 0;
                __syncthreads();
                sc[threadIdx.x] += v;
                __syncthreads();
            }
            if (m) {
                int p = base + sc[threadIdx.x] - 1;
                if (p < CAPE) { g_pos[t * 2 + s] = p;  g_gv[t * 2 + s] = g_gate[t * 2 + s]; }
                else          { g_pos[t * 2 + s] = -1; g_gv[t * 2 + s] = 0.f; }
            }
            base += sc[1023];
            __syncthreads();
        }
    }
}

// ---------------- dispatch: scatter x rows as packed bf16 hi/lo planes ----------
__global__ void dispatch_kernel(const float* __restrict__ x)
{
    int ts = blockIdx.x;
    int t = ts >> 1, s = ts & 1;
    int p = g_pos[t * 2 + s];
    if (p < 0) return;
    int e = g_idx[t * 2 + s];
    const float4* src = reinterpret_cast<const float4*>(x + (size_t)t * DM);
    size_t ro = ((size_t)e * CAPE + p) * (DM / 2);
    uint4* dhi = reinterpret_cast<uint4*>(g_disp_hi + ro);
    uint4* dlo = reinterpret_cast<uint4*>(g_disp_lo + ro);
    int j = threadIdx.x;
    float4 a = src[j * 2], b = src[j * 2 + 1];
    uint4 h, l;
    packsplit2(a.x, a.y, h.x, l.x);
    packsplit2(a.z, a.w, h.y, l.y);
    packsplit2(b.x, b.y, h.z, l.z);
    packsplit2(b.z, b.w, h.w, l.w);
    dhi[j] = h; dlo[j] = l;
}

// ---------------- weight pack + transpose: [E][K][N] fp32 -> [E][N][K/2] u32 ----
// tile 64k x 32n per block (256 thr = 32x8)
__global__ void packwT_kernel(const float* __restrict__ w, unsigned* __restrict__ whi,
                              unsigned* __restrict__ wlo, int K, int N)
{
    __shared__ float ts[64][33];
    int e = blockIdx.z;
    int k0 = blockIdx.y * 64, n0 = blockIdx.x * 32;
    int tx = threadIdx.x & 31, ty = threadIdx.x >> 5;
    const float* W = w + (size_t)e * K * N;
#pragma unroll
    for (int i = 0; i < 64; i += 8)
        ts[i + ty][tx] = W[(size_t)(k0 + i + ty) * N + n0 + tx];
    __syncthreads();
    unsigned* OH = whi + (size_t)e * (K / 2) * N;
    unsigned* OL = wlo + (size_t)e * (K / 2) * N;
#pragma unroll
    for (int j = 0; j < 4; j++) {
        int n = ty + j * 8;
        unsigned h, l;
        packsplit2(ts[2 * tx][n], ts[2 * tx + 1][n], h, l);
        size_t o = (size_t)(n0 + n) * (K / 2) + k0 / 2 + tx;
        OH[o] = h; OL[o] = l;
    }
}

// ---------------- bf16x3 tensor GEMM (ldmatrix fragments) -----------------------
// A planes [M][K2] u32, B planes [N][K2] u32, 128x128 tile, KC=16 u32 (32 k),
// 4-stage cp.async, 8 warps (4m x 2n), warp 32x64, ldmatrix.x4 everywhere.
#define K2C 16
#define RSTR 20               // smem row stride (u32) for both A and B
#define OFF_ALO 2560
#define OFF_BHI 5120
#define OFF_BLO 7680
#define SS 10240
#define NSTAGE 4
#define GEMM_SMEM (NSTAGE * SS * 4)

template <bool PACK>
__global__ void __launch_bounds__(256, 1)
mma_gemm(const unsigned* __restrict__ Ahi_, const unsigned* __restrict__ Alo_,
         const unsigned* __restrict__ Bhi_, const unsigned* __restrict__ Blo_,
         const float* __restrict__ biasb, float* __restrict__ Cf,
         unsigned* __restrict__ Ohi, unsigned* __restrict__ Olo,
         int M, int N, int K2)
{
    extern __shared__ unsigned sm[];
    uint32_t smem_base = smem_u32(sm);
    int tid = threadIdx.x;
    int lane = tid & 31, wid = tid >> 5;
    int wm = wid & 3, wn = wid >> 2;
    int g = lane >> 2, t4 = lane & 3;

    int z = blockIdx.z;
    const unsigned* Ahi = Ahi_ + (size_t)z * M * K2;
    const unsigned* Alo = Alo_ + (size_t)z * M * K2;
    const unsigned* Bhi = Bhi_ + (size_t)z * N * K2;
    const unsigned* Blo = Blo_ + (size_t)z * N * K2;
    const float* bias = biasb + (size_t)z * N;
    int brow = blockIdx.y * 128;
    int bcol = blockIdx.x * 128;

    float4 acc[2][8];
#pragma unroll
    for (int mi = 0; mi < 2; mi++)
#pragma unroll
        for (int tn = 0; tn < 8; tn++) acc[mi][tn] = make_float4(0.f, 0.f, 0.f, 0.f);

    // ldmatrix per-lane byte offsets (within a stage)
    const uint32_t a_off = ((uint32_t)(wm * 32 + (lane & 15)) * RSTR + ((lane >> 4) << 2)) * 4;
    const uint32_t b_off = (uint32_t)OFF_BHI * 4 +
        ((uint32_t)(wn * 64 + (lane & 7) + ((lane >> 4) << 3)) * RSTR + (((lane >> 3) & 1) << 2)) * 4;

    auto fill = [&](int st, int cc) {
        uint32_t base = smem_base + (uint32_t)st * (SS * 4);
#pragma unroll
        for (int i = 0; i < 2; i++) {
            int f = tid + i * 256;
            int row = f >> 2, q = f & 3;
            size_t soA = (size_t)(brow + row) * K2 + cc * K2C + q * 4;
            uint32_t d = base + (uint32_t)(row * RSTR + q * 4) * 4;
            cp16(d, Ahi + soA);
            cp16(d + OFF_ALO * 4, Alo + soA);
            size_t soB = (size_t)(bcol + row) * K2 + cc * K2C + q * 4;
            uint32_t dB = base + OFF_BHI * 4 + (uint32_t)(row * RSTR + q * 4) * 4;
            cp16(dB, Bhi + soB);
            cp16(dB + (OFF_BLO - OFF_BHI) * 4, Blo + soB);
        }
        asm volatile("cp.async.commit_group;" ::: "memory");
    };

    int nch = K2 / K2C;
    fill(0, 0); fill(1, 1); fill(2, 2);

    for (int c = 0; c < nch; ++c) {
        asm volatile("cp.async.wait_group 2;" ::: "memory");
        __syncthreads();
        if (c + 3 < nch) fill((c + 3) & 3, c + 3);

        uint32_t sbase = smem_base + (uint32_t)(c & 3) * (SS * 4);
#pragma unroll
        for (int ks = 0; ks < 2; ks++) {
            unsigned ah[2][4], al[2][4];
            ldsm4(ah[0], sbase + a_off + (ks * 8) * 4);
            ldsm4(ah[1], sbase + a_off + (16 * RSTR + ks * 8) * 4);
            ldsm4(al[0], sbase + a_off + (OFF_ALO + ks * 8) * 4);
            ldsm4(al[1], sbase + a_off + (OFF_ALO + 16 * RSTR + ks * 8) * 4);
#pragma unroll
            for (int tnp = 0; tnp < 4; tnp++) {
                unsigned bh[4], bl[4];
                ldsm4(bh, sbase + b_off + (tnp * 16 * RSTR + ks * 8) * 4);
                ldsm4(bl, sbase + b_off + ((OFF_BLO - OFF_BHI) + tnp * 16 * RSTR + ks * 8) * 4);
#pragma unroll
                for (int mi = 0; mi < 2; mi++) {
                    mma16(acc[mi][2 * tnp + 0], ah[mi], bh[0], bh[1]);   // hi*hi
                    mma16(acc[mi][2 * tnp + 0], ah[mi], bl[0], bl[1]);   // hi*lo
                    mma16(acc[mi][2 * tnp + 0], al[mi], bh[0], bh[1]);   // lo*hi
                    mma16(acc[mi][2 * tnp + 1], ah[mi], bh[2], bh[3]);
                    mma16(acc[mi][2 * tnp + 1], ah[mi], bl[2], bl[3]);
                    mma16(acc[mi][2 * tnp + 1], al[mi], bh[2], bh[3]);
                }
            }
        }
    }

    // ---- epilogue ----
    if (PACK) {
        unsigned* ohi = Ohi + (size_t)z * M * (N / 2);
        unsigned* olo = Olo + (size_t)z * M * (N / 2);
#pragma unroll
        for (int mi = 0; mi < 2; mi++) {
            int row = brow + wm * 32 + mi * 16 + g;
#pragma unroll
            for (int tn = 0; tn < 8; tn++) {
                int col = bcol + wn * 64 + tn * 8 + t4 * 2;
                float2 bv = *reinterpret_cast<const float2*>(bias + col);
                float v0 = acc[mi][tn].x + bv.x, v1 = acc[mi][tn].y + bv.y;
                float v2 = acc[mi][tn].z + bv.x, v3 = acc[mi][tn].w + bv.y;
                v0 = 0.5f * v0 * (1.f + erff(v0 * 0.70710678118654752f));
                v1 = 0.5f * v1 * (1.f + erff(v1 * 0.70710678118654752f));
                v2 = 0.5f * v2 * (1.f + erff(v2 * 0.70710678118654752f));
                v3 = 0.5f * v3 * (1.f + erff(v3 * 0.70710678118654752f));
                int col2 = col >> 1;
                unsigned h, l;
                packsplit2(v0, v1, h, l);
                ohi[(size_t)row * (N / 2) + col2] = h;
                olo[(size_t)row * (N / 2) + col2] = l;
                packsplit2(v2, v3, h, l);
                ohi[(size_t)(row + 8) * (N / 2) + col2] = h;
                olo[(size_t)(row + 8) * (N / 2) + col2] = l;
            }
        }
    } else {
        float* C = Cf + (size_t)z * M * N;
#pragma unroll
        for (int mi = 0; mi < 2; mi++) {
            int row = brow + wm * 32 + mi * 16 + g;
#pragma unroll
            for (int tn = 0; tn < 8; tn++) {
                int col = bcol + wn * 64 + tn * 8 + t4 * 2;
                float2 bv = *reinterpret_cast<const float2*>(bias + col);
                float2 v0, v1;
                v0.x = acc[mi][tn].x + bv.x;  v0.y = acc[mi][tn].y + bv.y;
                v1.x = acc[mi][tn].z + bv.x;  v1.y = acc[mi][tn].w + bv.y;
                *reinterpret_cast<float2*>(C + (size_t)row * N + col) = v0;
                *reinterpret_cast<float2*>(C + (size_t)(row + 8) * N + col) = v1;
            }
        }
    }
}

// ---------------- combine -------------------------------------------------------
__global__ void combine_kernel(float* __restrict__ y)
{
    int t = blockIdx.x;
    int e0 = g_idx[t * 2], e1 = g_idx[t * 2 + 1];
    int p0 = g_pos[t * 2], p1 = g_pos[t * 2 + 1];
    float w0 = g_gv[t * 2], w1 = g_gv[t * 2 + 1];
    const float* r0 = (p0 >= 0) ? g_eo + ((size_t)e0 * CAPE + p0) * DM : nullptr;
    const float* r1 = (p1 >= 0) ? g_eo + ((size_t)e1 * CAPE + p1) * DM : nullptr;
    float* yr = y + (size_t)t * DM;
    for (int d = threadIdx.x * 4; d < DM; d += blockDim.x * 4) {
        float4 a = make_float4(0.f, 0.f, 0.f, 0.f);
        if (r0) {
            float4 v = *reinterpret_cast<const float4*>(r0 + d);
            a.x = fmaf(w0, v.x, a.x); a.y = fmaf(w0, v.y, a.y);
            a.z = fmaf(w0, v.z, a.z); a.w = fmaf(w0, v.w, a.w);
        }
        if (r1) {
            float4 v = *reinterpret_cast<const float4*>(r1 + d);
            a.x = fmaf(w1, v.x, a.x); a.y = fmaf(w1, v.y, a.y);
            a.z = fmaf(w1, v.z, a.z); a.w = fmaf(w1, v.w, a.w);
        }
        *reinterpret_cast<float4*>(yr + d) = a;
    }
}

// ---------------- launch ---------------------------------------------------------
extern "C" void kernel_launch(void* const* d_in, const int* in_sizes, int n_in,
                              void* d_out, int out_size)
{
    const float* x    = (const float*)d_in[0];
    const float* wg   = (const float*)d_in[1];
    const float* fc1w = (const float*)d_in[2];
    const float* fc1b = (const float*)d_in[3];
    const float* fc2w = (const float*)d_in[4];
    const float* fc2b = (const float*)d_in[5];
    float* y = (float*)d_out;

    unsigned *dhi, *dlo, *hhi, *hlo, *w1h, *w1l, *w2h, *w2l;
    float* eo;
    cudaGetSymbolAddress((void**)&dhi, g_disp_hi);
    cudaGetSymbolAddress((void**)&dlo, g_disp_lo);
    cudaGetSymbolAddress((void**)&hhi, g_h_hi);
    cudaGetSymbolAddress((void**)&hlo, g_h_lo);
    cudaGetSymbolAddress((void**)&w1h, g_w1hi);
    cudaGetSymbolAddress((void**)&w1l, g_w1lo);
    cudaGetSymbolAddress((void**)&w2h, g_w2hi);
    cudaGetSymbolAddress((void**)&w2l, g_w2lo);
    cudaGetSymbolAddress((void**)&eo,  g_eo);

    cudaFuncSetAttribute(mma_gemm<true>,  cudaFuncAttributeMaxDynamicSharedMemorySize, GEMM_SMEM);
    cudaFuncSetAttribute(mma_gemm<false>, cudaFuncAttributeMaxDynamicSharedMemorySize, GEMM_SMEM);

    // weight packing (transposed hi/lo bf16 planes: [e][n][k2])
    packwT_kernel<<<dim3(HID / 32, DM / 64, NE), 256>>>(fc1w, w1h, w1l, DM, HID);
    packwT_kernel<<<dim3(DM / 32, HID / 64, NE), 256>>>(fc2w, w2h, w2l, HID, DM);

    gate_kernel<<<STOK / 8, 256>>>(x, wg);
    pos_kernel<<<NE, 1024>>>();
    dispatch_kernel<<<STOK * 2, 256>>>(x);

    dim3 g1(HID / 128, CAPE / 128, NE);   // fc1 + gelu -> packed h
    mma_gemm<true><<<g1, 256, GEMM_SMEM>>>(dhi, dlo, w1h, w1l, fc1b,
                                           nullptr, hhi, hlo, CAPE, HID, DM / 2);

    dim3 g2(DM / 128, CAPE / 128, NE);    // fc2 -> fp32 eo
    mma_gemm<false><<<g2, 256, GEMM_SMEM>>>(hhi, hlo, w2h, w2l, fc2b,
                                            eo, nullptr, nullptr, CAPE, DM, HID / 2);

    combine_kernel<<<STOK, 256>>>(y);
}